// round 3
// baseline (speedup 1.0000x reference)
#include <cuda_runtime.h>
#include <cuda_bf16.h>
#include <math.h>

// Problem constants
#define N_PROP   2048
#define N_CLS    81
#define N_FG     80
#define IMG_W    1333.0f
#define IMG_H    800.0f
#define SCORE_TH 0.05f
#define NMS_TH   0.5f
#define DETS     100
#define BBOX_CLIP 4.135166556742356f   // log(1000/16)
#define FLAT_TOT (N_FG * N_PROP)       // 163840

#define CAP3  16384                    // global candidate capacity
#define MAXC  2048                     // per-class candidate capacity
#define BITC  512                      // bitmask-NMS fast-path capacity
#define NW    (BITC / 64)              // 8 mask words per row
#define NTHR  512

typedef unsigned long long u64;
typedef unsigned int u32;
typedef unsigned short u16;
typedef unsigned char u8;

// ------------------- device scratch -------------------
__device__ float  g_rowmax[N_PROP];
__device__ float  g_rowsum[N_PROP];
__device__ float4 g_prop[N_PROP];            // w, h, cx, cy
__device__ int    g_cnt;
__device__ u64    g_cand[CAP3];              // key = ord(score)<<32 | (~flat)
__device__ u32    g_bar = 0;                 // monotonic grid-barrier ticket counter

// ------------------- helpers -------------------
__device__ __forceinline__ u32 ord32(float f) {
    u32 u = __float_as_uint(f);
    return (u & 0x80000000u) ? ~u : (u | 0x80000000u);
}
__device__ __forceinline__ float unord32(u32 u) {
    u32 b = (u & 0x80000000u) ? (u & 0x7FFFFFFFu) : ~u;
    return __uint_as_float(b);
}

__device__ __forceinline__ void grid_barrier() {
    __syncthreads();
    if (threadIdx.x == 0) {
        __threadfence();
        u32 ticket = atomicAdd(&g_bar, 1) + 1;
        u32 goal = ((ticket + N_FG - 1) / N_FG) * N_FG;   // next multiple of 80
        while ((int)(*(volatile u32*)&g_bar - goal) < 0) { }
        __threadfence();
    }
    __syncthreads();
}

__device__ __forceinline__ float4 decode_clip(const float* __restrict__ reg, int n, int cls) {
    float4 p = g_prop[n];  // w, h, cx, cy
    const float* r = reg + n * (N_CLS * 4) + cls * 4;
    float dx = r[0] / 10.0f;
    float dy = r[1] / 10.0f;
    float dw = fminf(r[2] / 5.0f, BBOX_CLIP);
    float dh = fminf(r[3] / 5.0f, BBOX_CLIP);
    float pcx = dx * p.x + p.z;
    float pcy = dy * p.y + p.w;
    float pw  = expf(dw) * p.x;
    float ph  = expf(dh) * p.y;
    float x1 = pcx - 0.5f * pw;
    float y1 = pcy - 0.5f * ph;
    float x2 = pcx + 0.5f * pw - 1.0f;
    float y2 = pcy + 0.5f * ph - 1.0f;
    x1 = fminf(fmaxf(x1, 0.0f), IMG_W - 1.0f);
    x2 = fminf(fmaxf(x2, 0.0f), IMG_W - 1.0f);
    y1 = fminf(fmaxf(y1, 0.0f), IMG_H - 1.0f);
    y2 = fminf(fmaxf(y2, 0.0f), IMG_H - 1.0f);
    return make_float4(x1, y1, x2, y2);
}

// descending bitonic sort, block-cooperative
__device__ __forceinline__ void bitonic_desc(u64* keys, int P, int tid) {
    for (int k = 2; k <= P; k <<= 1) {
        for (int j = k >> 1; j > 0; j >>= 1) {
            for (int i = tid; i < P; i += NTHR) {
                int ixj = i ^ j;
                if (ixj > i) {
                    u64 a = keys[i], b = keys[ixj];
                    bool desc = ((i & k) == 0);
                    if ((a < b) == desc) { keys[i] = b; keys[ixj] = a; }
                }
            }
            __syncthreads();
        }
    }
}

// ------------------- fused kernel: 80 blocks x 512 threads, single launch ----------
__global__ void __launch_bounds__(NTHR, 1)
fused_kernel(const float* __restrict__ logits,
             const float* __restrict__ reg,
             const float* __restrict__ props,
             float* __restrict__ out) {
    extern __shared__ char sm[];
    int tid = threadIdx.x;
    int bid = blockIdx.x;

    // ================= Phase A: softmax stats + proposal stats + reset ===========
    if (bid == 0 && tid == 0) g_cnt = 0;
    {
        int wid = tid >> 5, lane = tid & 31;
        int gwarp = bid * (NTHR / 32) + wid;               // 0..1279
        for (int row = gwarp; row < N_PROP; row += N_FG * (NTHR / 32)) {
            const float* lr = logits + row * N_CLS;
            int c2 = lane + 64;
            float l0 = lr[lane];
            float l1 = lr[lane + 32];
            float l2 = (c2 < N_CLS) ? lr[c2] : -3.0e38f;
            float m = fmaxf(fmaxf(l0, l1), l2);
            #pragma unroll
            for (int o = 16; o; o >>= 1) m = fmaxf(m, __shfl_xor_sync(0xFFFFFFFFu, m, o));
            float s = expf(l0 - m) + expf(l1 - m) + ((c2 < N_CLS) ? expf(l2 - m) : 0.0f);
            #pragma unroll
            for (int o = 16; o; o >>= 1) s += __shfl_xor_sync(0xFFFFFFFFu, s, o);
            if (lane == 0) {
                g_rowmax[row] = m;
                g_rowsum[row] = s;
                const float* p = props + row * 4;
                float w = p[2] - p[0] + 1.0f;
                float h = p[3] - p[1] + 1.0f;
                g_prop[row] = make_float4(w, h, p[0] + 0.5f * w, p[1] + 0.5f * h);
            }
        }
    }
    grid_barrier();

    // ================= Phase B: per-class threshold + sort + bitmask NMS =========
    {
        u64*    keys = (u64*)sm;                                 // [MAXC] 16KB
        float4* sbox = (float4*)(sm + MAXC * sizeof(u64));       // [MAXC] 32KB
        u64 (*mask)[NW] = (u64(*)[NW])(sm + MAXC * 24);          // [BITC][NW] 32KB
        u16* kept = (u16*)(sm + MAXC * 24 + BITC * NW * 8);      // [BITC] 1KB
        u8*  supp = (u8*)(sm + MAXC * 24 + BITC * NW * 8 + BITC * 2); // [MAXC]
        __shared__ int s_cnt, s_nk, s_base;

        int cls = bid + 1;  // foreground class 1..80
        if (tid == 0) s_cnt = 0;
        __syncthreads();

        // threshold: prob from logits directly (strided gather, L2-resident)
        for (int n = tid; n < N_PROP; n += NTHR) {
            float p = expf(logits[n * N_CLS + cls] - g_rowmax[n]) / g_rowsum[n];
            if (p > SCORE_TH) {
                int slot = atomicAdd(&s_cnt, 1);
                keys[slot] = ((u64)ord32(p) << 32) | (u64)(0xFFFFFFFFu - (u32)n);
            }
        }
        __syncthreads();

        int M = s_cnt;
        if (M > 0) {
            int P = 1;
            while (P < M) P <<= 1;
            if (P < 2) P = 2;
            for (int i = M + tid; i < P; i += NTHR) keys[i] = 0ULL;
            __syncthreads();

            bitonic_desc(keys, P, tid);  // desc score, asc proposal idx on ties

            for (int s = tid; s < M; s += NTHR) {
                u32 n = 0xFFFFFFFFu - (u32)(keys[s] & 0xFFFFFFFFu);
                sbox[s] = decode_clip(reg, (int)n, cls);
            }
            __syncthreads();

            if (M <= BITC) {
                // bitmask NMS
                for (int r = tid; r < M; r += NTHR) {
                    float4 bi = sbox[r];
                    float ai = (bi.z - bi.x + 1.0f) * (bi.w - bi.y + 1.0f);
                    u64 w[NW];
                    #pragma unroll
                    for (int q = 0; q < NW; q++) w[q] = 0ULL;
                    for (int j = r + 1; j < M; j++) {
                        float4 bj = sbox[j];
                        float xx1 = fmaxf(bi.x, bj.x);
                        float yy1 = fmaxf(bi.y, bj.y);
                        float xx2 = fminf(bi.z, bj.z);
                        float yy2 = fminf(bi.w, bj.w);
                        float iw = fmaxf(xx2 - xx1 + 1.0f, 0.0f);
                        float ih = fmaxf(yy2 - yy1 + 1.0f, 0.0f);
                        float inter = iw * ih;
                        float aj = (bj.z - bj.x + 1.0f) * (bj.w - bj.y + 1.0f);
                        if (inter / (ai + aj - inter) > NMS_TH)
                            w[j >> 6] |= 1ULL << (j & 63);
                    }
                    #pragma unroll
                    for (int q = 0; q < NW; q++) mask[r][q] = w[q];
                }
                __syncthreads();

                if (tid == 0) {
                    u64 rem[NW];
                    #pragma unroll
                    for (int q = 0; q < NW; q++) rem[q] = 0ULL;
                    int nk = 0;
                    for (int i = 0; i < M; i++) {
                        if (!((rem[i >> 6] >> (i & 63)) & 1ULL)) {
                            kept[nk++] = (u16)i;
                            for (int q = i >> 6; q < NW; q++) rem[q] |= mask[i][q];
                        }
                    }
                    s_nk = nk;
                    s_base = atomicAdd(&g_cnt, nk);
                }
                __syncthreads();

                int nk = s_nk, base = s_base;
                for (int t = tid; t < nk; t += NTHR) {
                    u64 key = keys[kept[t]];
                    u32 n = 0xFFFFFFFFu - (u32)(key & 0xFFFFFFFFu);
                    u32 flat = (u32)(cls - 1) * N_PROP + n;
                    if (base + t < CAP3)
                        g_cand[base + t] = (key & 0xFFFFFFFF00000000ULL) |
                                           (u64)(0xFFFFFFFFu - flat);
                }
            } else {
                // fallback serial greedy NMS (M > 512; never triggers on this input)
                for (int i = tid; i < M; i += NTHR) supp[i] = 0;
                __syncthreads();
                for (int i = 0; i < M; i++) {
                    if (!supp[i]) {
                        float4 bi = sbox[i];
                        float ai = (bi.z - bi.x + 1.0f) * (bi.w - bi.y + 1.0f);
                        if (tid == 0) {
                            u32 n = 0xFFFFFFFFu - (u32)(keys[i] & 0xFFFFFFFFu);
                            u32 flat = (u32)(cls - 1) * N_PROP + n;
                            int pos = atomicAdd(&g_cnt, 1);
                            if (pos < CAP3)
                                g_cand[pos] = (keys[i] & 0xFFFFFFFF00000000ULL) |
                                              (u64)(0xFFFFFFFFu - flat);
                        }
                        for (int j = i + 1 + tid; j < M; j += NTHR) {
                            if (!supp[j]) {
                                float4 bj = sbox[j];
                                float xx1 = fmaxf(bi.x, bj.x);
                                float yy1 = fmaxf(bi.y, bj.y);
                                float xx2 = fminf(bi.z, bj.z);
                                float yy2 = fminf(bi.w, bj.w);
                                float iw = fmaxf(xx2 - xx1 + 1.0f, 0.0f);
                                float ih = fmaxf(yy2 - yy1 + 1.0f, 0.0f);
                                float inter = iw * ih;
                                float aj = (bj.z - bj.x + 1.0f) * (bj.w - bj.y + 1.0f);
                                if (inter / (ai + aj - inter) > NMS_TH) supp[j] = 1;
                            }
                        }
                    }
                    __syncthreads();
                }
            }
        }
    }
    grid_barrier();

    // ================= Phase C: block 0 — exact radix-select top-100 =============
    if (bid != 0) return;
    {
        u64* keys = (u64*)sm;   // reuse smem: [CAP3] up to 128KB
        __shared__ u32 hist[256];
        __shared__ u64 s_prefix, s_T;
        __shared__ int s_r, s_cnt, s_K, s_selcnt;
        __shared__ u64 sel[DETS];

        int K = g_cnt;
        if (K > CAP3) K = CAP3;
        for (int i = tid; i < K; i += NTHR) keys[i] = g_cand[i];
        if (tid == 0) { s_prefix = 0ULL; s_r = DETS; s_selcnt = 0; s_K = K; }
        __syncthreads();

        // fallback fill (reference's -1-masked top_k): only when fewer than 100 kept
        if (tid == 0 && K < DETS) {
            int kk = K, f = 0;
            while (kk < DETS && f < FLAT_TOT) {
                bool found = false;
                for (int q = 0; q < K; q++) {
                    u32 fl = 0xFFFFFFFFu - (u32)(keys[q] & 0xFFFFFFFFu);
                    if ((int)fl == f) { found = true; break; }
                }
                if (!found)
                    keys[kk++] = ((u64)ord32(-1.0f) << 32) | (u64)(0xFFFFFFFFu - (u32)f);
                f++;
            }
            s_K = kk;
        }
        __syncthreads();
        K = s_K;

        // MSB-first 8-bit radix select of the exact 100th-largest key
        bool done = false;
        for (int shift = 56; shift >= 0 && !done; shift -= 8) {
            if (tid < 256) hist[tid] = 0;
            __syncthreads();
            u64 hm  = (shift == 56) ? 0ULL : (~0ULL) << (shift + 8);
            u64 pfx = s_prefix;
            for (int base = 0; base < K; base += NTHR) {
                int i = base + tid;
                bool v = (i < K);
                u64 k = v ? keys[i] : 0ULL;
                bool mt = v && ((k & hm) == pfx);
                u32 b = mt ? (u32)((k >> shift) & 255u) : 0xFFFFFFFFu;
                u32 grp = __match_any_sync(0xFFFFFFFFu, b);
                if (mt && ((__ffs(grp) - 1) == (tid & 31)))
                    atomicAdd(&hist[b], __popc(grp));
            }
            __syncthreads();
            if (tid < 32) {
                int r0 = s_r;
                __syncwarp();
                u32 h[8]; u32 cs = 0;
                #pragma unroll
                for (int q = 0; q < 8; q++) { h[q] = hist[tid * 8 + q]; cs += h[q]; }
                u32 p = cs;
                #pragma unroll
                for (int o = 1; o < 32; o <<= 1) {
                    u32 vv = __shfl_up_sync(0xFFFFFFFFu, p, o);
                    if (tid >= o) p += vv;
                }
                u32 total = __shfl_sync(0xFFFFFFFFu, p, 31);
                u32 run = total - p;   // keys in strictly-higher bins
                int chosen = -1; u32 newr = 0, cinb = 0;
                for (int q = 7; q >= 0; q--) {
                    if (chosen < 0 && run < (u32)r0 && (u32)r0 <= run + h[q]) {
                        chosen = tid * 8 + q; newr = (u32)r0 - run; cinb = h[q];
                    }
                    run += h[q];
                }
                if (chosen >= 0) {
                    s_prefix = pfx | ((u64)(u32)chosen << shift);
                    s_r = (int)newr;
                    s_cnt = (int)cinb;
                }
            }
            __syncthreads();
            if (s_cnt == 1) {
                u64 hm2 = (shift == 0) ? ~0ULL : (~0ULL) << shift;
                u64 pfx2 = s_prefix;
                for (int i = tid; i < K; i += NTHR) {
                    u64 k = keys[i];
                    if ((k & hm2) == pfx2) s_T = k;
                }
                done = true;
            }
            __syncthreads();
        }
        u64 T = s_T;

        // exactly 100 keys >= T (keys unique)
        for (int i = tid; i < K; i += NTHR) {
            u64 k = keys[i];
            if (k >= T) {
                int s = atomicAdd(&s_selcnt, 1);
                if (s < DETS) sel[s] = k;
            }
        }
        __syncthreads();

        if (tid < DETS) {
            u64 my = sel[tid];
            int rank = 0;
            for (int q = 0; q < DETS; q++) rank += (sel[q] > my);
            u32 flat = 0xFFFFFFFFu - (u32)(my & 0xFFFFFFFFu);
            float score = unord32((u32)(my >> 32));
            int c = (int)(flat >> 11);
            int n = (int)(flat & (N_PROP - 1));
            float4 b = decode_clip(reg, n, c + 1);
            out[rank * 4 + 0] = b.x;
            out[rank * 4 + 1] = b.y;
            out[rank * 4 + 2] = b.z;
            out[rank * 4 + 3] = b.w;
            out[DETS * 4 + rank] = score;
            out[DETS * 5 + rank] = (float)(c + 1);
        }
    }
}

// ------------------- launch -------------------
extern "C" void kernel_launch(void* const* d_in, const int* in_sizes, int n_in,
                              void* d_out, int out_size) {
    const float* logits = (const float*)d_in[0];  // [2048, 81]
    const float* reg    = (const float*)d_in[1];  // [2048, 324]
    const float* props  = (const float*)d_in[2];  // [2048, 4]
    float* out = (float*)d_out;                   // 600 floats

    size_t smem = (size_t)CAP3 * sizeof(u64);     // 128KB (covers phase B's 81KB too)
    cudaFuncSetAttribute(fused_kernel, cudaFuncAttributeMaxDynamicSharedMemorySize, (int)smem);
    fused_kernel<<<N_FG, NTHR, smem>>>(logits, reg, props, out);
}

// round 4
// speedup vs baseline: 1.7599x; 1.7599x over previous
#include <cuda_runtime.h>
#include <cuda_bf16.h>
#include <math.h>

#define N_PROP   2048
#define N_CLS    81
#define N_FG     80
#define IMG_W    1333.0f
#define IMG_H    800.0f
#define SCORE_TH 0.05f
#define NMS_TH   0.5f
#define DETS     100
#define BBOX_CLIP 4.135166556742356f   // log(1000/16)
#define FLAT_TOT (N_FG * N_PROP)

#define CAP3  16384
#define MAXC  2048
#define BITC  512
#define NWMAX (BITC / 64)              // 8
#define NTHR  512

typedef unsigned long long u64;
typedef unsigned int u32;
typedef unsigned short u16;
typedef unsigned char u8;

// ------------------- device scratch -------------------
__device__ float  g_rowmax[N_PROP];
__device__ float  g_rowsum[N_PROP];
__device__ float4 g_prop[N_PROP];            // w, h, cx, cy
__device__ int    g_cnt;
__device__ u64    g_cand[CAP3];              // key = ord(score)<<32 | (~flat)
__device__ u32    g_bar = 0;                 // monotonic ticket counter

// ------------------- helpers -------------------
__device__ __forceinline__ u32 ord32(float f) {
    u32 u = __float_as_uint(f);
    return (u & 0x80000000u) ? ~u : (u | 0x80000000u);
}
__device__ __forceinline__ float unord32(u32 u) {
    u32 b = (u & 0x80000000u) ? (u & 0x7FFFFFFFu) : ~u;
    return __uint_as_float(b);
}

__device__ __forceinline__ void grid_barrier() {
    __threadfence();
    __syncthreads();
    if (threadIdx.x == 0) {
        u32 ticket = atomicAdd(&g_bar, 1) + 1;
        u32 goal = ((ticket + N_FG - 1) / N_FG) * N_FG;
        while ((int)(*(volatile u32*)&g_bar - goal) < 0) { }
        __threadfence();
    }
    __syncthreads();
}

__device__ __forceinline__ float4 decode_clip(const float* __restrict__ reg, int n, int cls) {
    float4 p = g_prop[n];
    const float* r = reg + n * (N_CLS * 4) + cls * 4;
    float dx = r[0] / 10.0f;
    float dy = r[1] / 10.0f;
    float dw = fminf(r[2] / 5.0f, BBOX_CLIP);
    float dh = fminf(r[3] / 5.0f, BBOX_CLIP);
    float pcx = dx * p.x + p.z;
    float pcy = dy * p.y + p.w;
    float pw  = expf(dw) * p.x;
    float ph  = expf(dh) * p.y;
    float x1 = pcx - 0.5f * pw;
    float y1 = pcy - 0.5f * ph;
    float x2 = pcx + 0.5f * pw - 1.0f;
    float y2 = pcy + 0.5f * ph - 1.0f;
    x1 = fminf(fmaxf(x1, 0.0f), IMG_W - 1.0f);
    x2 = fminf(fmaxf(x2, 0.0f), IMG_W - 1.0f);
    y1 = fminf(fmaxf(y1, 0.0f), IMG_H - 1.0f);
    y2 = fminf(fmaxf(y2, 0.0f), IMG_H - 1.0f);
    return make_float4(x1, y1, x2, y2);
}

__device__ __forceinline__ void bitonic_desc(u64* keys, int P, int tid) {
    for (int k = 2; k <= P; k <<= 1) {
        for (int j = k >> 1; j > 0; j >>= 1) {
            for (int i = tid; i < P; i += NTHR) {
                int ixj = i ^ j;
                if (ixj > i) {
                    u64 a = keys[i], b = keys[ixj];
                    bool desc = ((i & k) == 0);
                    if ((a < b) == desc) { keys[i] = b; keys[ixj] = a; }
                }
            }
            __syncthreads();
        }
    }
}

// ------------------- fused kernel: 80 blocks x 512 threads -------------------
__global__ void __launch_bounds__(NTHR, 1)
fused_kernel(const float* __restrict__ logits,
             const float* __restrict__ reg,
             const float* __restrict__ props,
             float* __restrict__ out) {
    extern __shared__ char sm[];
    int tid = threadIdx.x;
    int bid = blockIdx.x;

    // ========== Phase A: softmax stats + proposal stats ==========
    if (bid == 0 && tid == 0) g_cnt = 0;
    {
        int wid = tid >> 5, lane = tid & 31;
        int gwarp = bid * (NTHR / 32) + wid;
        for (int row = gwarp; row < N_PROP; row += N_FG * (NTHR / 32)) {
            const float* lr = logits + row * N_CLS;
            int c2 = lane + 64;
            float l0 = lr[lane];
            float l1 = lr[lane + 32];
            float l2 = (c2 < N_CLS) ? lr[c2] : -3.0e38f;
            float m = fmaxf(fmaxf(l0, l1), l2);
            #pragma unroll
            for (int o = 16; o; o >>= 1) m = fmaxf(m, __shfl_xor_sync(0xFFFFFFFFu, m, o));
            float s = expf(l0 - m) + expf(l1 - m) + ((c2 < N_CLS) ? expf(l2 - m) : 0.0f);
            #pragma unroll
            for (int o = 16; o; o >>= 1) s += __shfl_xor_sync(0xFFFFFFFFu, s, o);
            if (lane == 0) {
                g_rowmax[row] = m;
                g_rowsum[row] = s;
                const float* p = props + row * 4;
                float w = p[2] - p[0] + 1.0f;
                float h = p[3] - p[1] + 1.0f;
                g_prop[row] = make_float4(w, h, p[0] + 0.5f * w, p[1] + 0.5f * h);
            }
        }
    }
    grid_barrier();

    // ========== Phase B: per-class threshold + sort + bitmask NMS ==========
    {
        u64*    keys  = (u64*)sm;                                  // 16KB
        float4* sbox  = (float4*)(sm + MAXC * 8);                  // 32KB
        float*  sarea = (float*)(sm + MAXC * 24);                  // 8KB
        u64 (*mask)[NWMAX] = (u64(*)[NWMAX])(sm + MAXC * 28);      // 32KB
        u16* kept = (u16*)(sm + MAXC * 28 + BITC * NWMAX * 8);     // 1KB
        u8*  supp = (u8*)(sm + MAXC * 28 + BITC * NWMAX * 8 + BITC * 2);
        __shared__ int s_cnt, s_nk, s_base;

        int cls = bid + 1;
        if (tid == 0) s_cnt = 0;
        __syncthreads();

        for (int n = tid; n < N_PROP; n += NTHR) {
            float p = expf(logits[n * N_CLS + cls] - g_rowmax[n]) / g_rowsum[n];
            if (p > SCORE_TH) {
                int slot = atomicAdd(&s_cnt, 1);
                keys[slot] = ((u64)ord32(p) << 32) | (u64)(0xFFFFFFFFu - (u32)n);
            }
        }
        __syncthreads();

        int M = s_cnt;
        if (M > 0) {
            int P = 1;
            while (P < M) P <<= 1;
            if (P < 2) P = 2;
            for (int i = M + tid; i < P; i += NTHR) keys[i] = 0ULL;
            __syncthreads();

            bitonic_desc(keys, P, tid);

            for (int s = tid; s < M; s += NTHR) {
                u32 n = 0xFFFFFFFFu - (u32)(keys[s] & 0xFFFFFFFFu);
                float4 b = decode_clip(reg, (int)n, cls);
                sbox[s] = b;
                sarea[s] = (b.z - b.x + 1.0f) * (b.w - b.y + 1.0f);
            }
            __syncthreads();

            if (M <= BITC) {
                int nw = (M + 63) >> 6;
                // ---- mask rows: per-word scalar accumulation (no local mem, no div) ----
                for (int r = tid; r < M; r += NTHR) {
                    float4 bi = sbox[r];
                    float ai = sarea[r];
                    for (int q = 0; q < nw; q++) {
                        u64 wq = 0ULL;
                        int jlo = q << 6; if (jlo < r + 1) jlo = r + 1;
                        int jhi = (q << 6) + 64; if (jhi > M) jhi = M;
                        for (int j = jlo; j < jhi; j++) {
                            float4 bj = sbox[j];
                            float xx1 = fmaxf(bi.x, bj.x);
                            float yy1 = fmaxf(bi.y, bj.y);
                            float xx2 = fminf(bi.z, bj.z);
                            float yy2 = fminf(bi.w, bj.w);
                            float iw = fmaxf(xx2 - xx1 + 1.0f, 0.0f);
                            float ih = fmaxf(yy2 - yy1 + 1.0f, 0.0f);
                            float inter = iw * ih;
                            // inter/union > 0.5  <=>  inter > 0.5*union (0.5x exact)
                            if (inter > NMS_TH * (ai + sarea[j] - inter))
                                wq |= 1ULL << (j & 63);
                        }
                        mask[r][q] = wq;
                    }
                }
                __syncthreads();

                // ---- greedy scan ----
                if (M <= 64) {
                    // scalar, single-register rem
                    if (tid == 0) {
                        u64 rem = 0ULL;
                        int nk = 0;
                        for (int i = 0; i < M; i++) {
                            if (!((rem >> i) & 1ULL)) {
                                kept[nk++] = (u16)i;
                                rem |= mask[i][0];
                            }
                        }
                        s_nk = nk;
                        s_base = atomicAdd(&g_cnt, nk);
                    }
                } else if (tid < 32) {
                    // warp-cooperative: lane q owns rem word q (register)
                    int lane = tid;
                    u64 rem = 0ULL;
                    int nk = 0;
                    for (int i = 0; i < M; i++) {
                        u64 rw = __shfl_sync(0xFFFFFFFFu, rem, i >> 6);
                        if (!((rw >> (i & 63)) & 1ULL)) {
                            if (lane == 0) kept[nk] = (u16)i;
                            nk++;
                            if (lane < NWMAX) rem |= mask[i][lane];
                        }
                    }
                    if (lane == 0) {
                        s_nk = nk;
                        s_base = atomicAdd(&g_cnt, nk);
                    }
                }
                __syncthreads();

                int nk = s_nk, base = s_base;
                for (int t = tid; t < nk; t += NTHR) {
                    u64 key = keys[kept[t]];
                    u32 n = 0xFFFFFFFFu - (u32)(key & 0xFFFFFFFFu);
                    u32 flat = (u32)(cls - 1) * N_PROP + n;
                    if (base + t < CAP3)
                        g_cand[base + t] = (key & 0xFFFFFFFF00000000ULL) |
                                           (u64)(0xFFFFFFFFu - flat);
                }
            } else {
                // fallback serial greedy NMS (never triggers on this input)
                for (int i = tid; i < M; i += NTHR) supp[i] = 0;
                __syncthreads();
                for (int i = 0; i < M; i++) {
                    if (!supp[i]) {
                        float4 bi = sbox[i];
                        float ai = sarea[i];
                        if (tid == 0) {
                            u32 n = 0xFFFFFFFFu - (u32)(keys[i] & 0xFFFFFFFFu);
                            u32 flat = (u32)(cls - 1) * N_PROP + n;
                            int pos = atomicAdd(&g_cnt, 1);
                            if (pos < CAP3)
                                g_cand[pos] = (keys[i] & 0xFFFFFFFF00000000ULL) |
                                              (u64)(0xFFFFFFFFu - flat);
                        }
                        for (int j = i + 1 + tid; j < M; j += NTHR) {
                            if (!supp[j]) {
                                float4 bj = sbox[j];
                                float xx1 = fmaxf(bi.x, bj.x);
                                float yy1 = fmaxf(bi.y, bj.y);
                                float xx2 = fminf(bi.z, bj.z);
                                float yy2 = fminf(bi.w, bj.w);
                                float iw = fmaxf(xx2 - xx1 + 1.0f, 0.0f);
                                float ih = fmaxf(yy2 - yy1 + 1.0f, 0.0f);
                                float inter = iw * ih;
                                if (inter > NMS_TH * (ai + sarea[j] - inter)) supp[j] = 1;
                            }
                        }
                    }
                    __syncthreads();
                }
            }
        }
    }
    grid_barrier();

    // ========== Phase C: block 0 — exact radix-select top-100 ==========
    if (bid != 0) return;
    {
        u64* keys = (u64*)sm;   // reuse: up to 128KB
        __shared__ u32 hist[256];
        __shared__ u64 s_prefix, s_T;
        __shared__ int s_r, s_cnt, s_K, s_selcnt;
        __shared__ u64 sel[DETS];

        int K = g_cnt;
        if (K > CAP3) K = CAP3;
        for (int i = tid; i < K; i += NTHR) keys[i] = g_cand[i];
        if (tid == 0) { s_prefix = 0ULL; s_r = DETS; s_selcnt = 0; s_K = K; s_cnt = 0; }
        __syncthreads();

        if (tid == 0 && K < DETS) {
            int kk = K, f = 0;
            while (kk < DETS && f < FLAT_TOT) {
                bool found = false;
                for (int q = 0; q < K; q++) {
                    u32 fl = 0xFFFFFFFFu - (u32)(keys[q] & 0xFFFFFFFFu);
                    if ((int)fl == f) { found = true; break; }
                }
                if (!found)
                    keys[kk++] = ((u64)ord32(-1.0f) << 32) | (u64)(0xFFFFFFFFu - (u32)f);
                f++;
            }
            s_K = kk;
        }
        __syncthreads();
        K = s_K;

        bool done = false;
        for (int shift = 56; shift >= 0 && !done; shift -= 8) {
            if (tid < 256) hist[tid] = 0;
            __syncthreads();
            u64 hm  = (shift == 56) ? 0ULL : (~0ULL) << (shift + 8);
            u64 pfx = s_prefix;
            for (int base = 0; base < K; base += NTHR) {
                int i = base + tid;
                bool v = (i < K);
                u64 k = v ? keys[i] : 0ULL;
                bool mt = v && ((k & hm) == pfx);
                u32 b = mt ? (u32)((k >> shift) & 255u) : 0xFFFFFFFFu;
                u32 grp = __match_any_sync(0xFFFFFFFFu, b);
                if (mt && ((__ffs(grp) - 1) == (tid & 31)))
                    atomicAdd(&hist[b], __popc(grp));
            }
            __syncthreads();
            if (tid < 32) {
                int r0 = s_r;
                __syncwarp();
                u32 h[8]; u32 cs = 0;
                #pragma unroll
                for (int q = 0; q < 8; q++) { h[q] = hist[tid * 8 + q]; cs += h[q]; }
                u32 p = cs;
                #pragma unroll
                for (int o = 1; o < 32; o <<= 1) {
                    u32 vv = __shfl_up_sync(0xFFFFFFFFu, p, o);
                    if (tid >= o) p += vv;
                }
                u32 total = __shfl_sync(0xFFFFFFFFu, p, 31);
                u32 run = total - p;
                int chosen = -1; u32 newr = 0, cinb = 0;
                #pragma unroll
                for (int q = 7; q >= 0; q--) {
                    if (chosen < 0 && run < (u32)r0 && (u32)r0 <= run + h[q]) {
                        chosen = tid * 8 + q; newr = (u32)r0 - run; cinb = h[q];
                    }
                    run += h[q];
                }
                if (chosen >= 0) {
                    s_prefix = pfx | ((u64)(u32)chosen << shift);
                    s_r = (int)newr;
                    s_cnt = (int)cinb;
                }
            }
            __syncthreads();
            if (s_cnt == 1) {
                u64 hm2 = (shift == 0) ? ~0ULL : (~0ULL) << shift;
                u64 pfx2 = s_prefix;
                for (int i = tid; i < K; i += NTHR) {
                    u64 k = keys[i];
                    if ((k & hm2) == pfx2) s_T = k;
                }
                done = true;
            }
            __syncthreads();
        }
        u64 T = s_T;

        for (int i = tid; i < K; i += NTHR) {
            u64 k = keys[i];
            if (k >= T) {
                int s = atomicAdd(&s_selcnt, 1);
                if (s < DETS) sel[s] = k;
            }
        }
        __syncthreads();

        if (tid < DETS) {
            u64 my = sel[tid];
            int rank = 0;
            for (int q = 0; q < DETS; q++) rank += (sel[q] > my);
            u32 flat = 0xFFFFFFFFu - (u32)(my & 0xFFFFFFFFu);
            float score = unord32((u32)(my >> 32));
            int c = (int)(flat >> 11);
            int n = (int)(flat & (N_PROP - 1));
            float4 b = decode_clip(reg, n, c + 1);
            out[rank * 4 + 0] = b.x;
            out[rank * 4 + 1] = b.y;
            out[rank * 4 + 2] = b.z;
            out[rank * 4 + 3] = b.w;
            out[DETS * 4 + rank] = score;
            out[DETS * 5 + rank] = (float)(c + 1);
        }
    }
}

// ------------------- launch -------------------
extern "C" void kernel_launch(void* const* d_in, const int* in_sizes, int n_in,
                              void* d_out, int out_size) {
    const float* logits = (const float*)d_in[0];
    const float* reg    = (const float*)d_in[1];
    const float* props  = (const float*)d_in[2];
    float* out = (float*)d_out;

    size_t smem = (size_t)CAP3 * sizeof(u64);  // 128KB
    cudaFuncSetAttribute(fused_kernel, cudaFuncAttributeMaxDynamicSharedMemorySize, (int)smem);
    fused_kernel<<<N_FG, NTHR, smem>>>(logits, reg, props, out);
}

// round 5
// speedup vs baseline: 2.0234x; 1.1497x over previous
#include <cuda_runtime.h>
#include <cuda_bf16.h>
#include <math.h>

#define N_PROP   2048
#define N_CLS    81
#define N_FG     80
#define IMG_W    1333.0f
#define IMG_H    800.0f
#define SCORE_TH 0.05f
#define NMS_TH   0.5f
#define DETS     100
#define BBOX_CLIP 4.135166556742356f   // log(1000/16)
#define FLAT_TOT (N_FG * N_PROP)

#define CAP3  16384
#define MAXC  2048
#define BITC  512
#define NWMAX (BITC / 64)              // 8
#define NTHR  512
#define EXTC  256                      // phase-C early-exit bucket capacity

typedef unsigned long long u64;
typedef unsigned int u32;
typedef unsigned short u16;
typedef unsigned char u8;

// ------------------- device scratch -------------------
__device__ float  g_rowmax[N_PROP];
__device__ float  g_rowsum[N_PROP];
__device__ float4 g_prop[N_PROP];            // w, h, cx, cy
__device__ int    g_cnt;
__device__ u64    g_cand[CAP3];              // key = ord(score)<<32 | (~flat)
__device__ u32    g_bar = 0;                 // monotonic ticket counter

// ------------------- helpers -------------------
__device__ __forceinline__ u32 ord32(float f) {
    u32 u = __float_as_uint(f);
    return (u & 0x80000000u) ? ~u : (u | 0x80000000u);
}
__device__ __forceinline__ float unord32(u32 u) {
    u32 b = (u & 0x80000000u) ? (u & 0x7FFFFFFFu) : ~u;
    return __uint_as_float(b);
}

__device__ __forceinline__ void grid_barrier() {
    __threadfence();
    __syncthreads();
    if (threadIdx.x == 0) {
        u32 ticket = atomicAdd(&g_bar, 1) + 1;
        u32 goal = ((ticket + N_FG - 1) / N_FG) * N_FG;
        while ((int)(*(volatile u32*)&g_bar - goal) < 0) { }
        __threadfence();
    }
    __syncthreads();
}

__device__ __forceinline__ float4 decode_clip(const float* __restrict__ reg, int n, int cls) {
    float4 p = g_prop[n];
    const float* r = reg + n * (N_CLS * 4) + cls * 4;
    float dx = r[0] / 10.0f;
    float dy = r[1] / 10.0f;
    float dw = fminf(r[2] / 5.0f, BBOX_CLIP);
    float dh = fminf(r[3] / 5.0f, BBOX_CLIP);
    float pcx = dx * p.x + p.z;
    float pcy = dy * p.y + p.w;
    float pw  = expf(dw) * p.x;
    float ph  = expf(dh) * p.y;
    float x1 = pcx - 0.5f * pw;
    float y1 = pcy - 0.5f * ph;
    float x2 = pcx + 0.5f * pw - 1.0f;
    float y2 = pcy + 0.5f * ph - 1.0f;
    x1 = fminf(fmaxf(x1, 0.0f), IMG_W - 1.0f);
    x2 = fminf(fmaxf(x2, 0.0f), IMG_W - 1.0f);
    y1 = fminf(fmaxf(y1, 0.0f), IMG_H - 1.0f);
    y2 = fminf(fmaxf(y2, 0.0f), IMG_H - 1.0f);
    return make_float4(x1, y1, x2, y2);
}

// warp softmax reduction over one row's 3 register slices
__device__ __forceinline__ void row_softmax(float l0, float l1, float l2, bool has2,
                                            float& m_out, float& s_out) {
    float m = fmaxf(fmaxf(l0, l1), has2 ? l2 : -3.0e38f);
    #pragma unroll
    for (int o = 16; o; o >>= 1) m = fmaxf(m, __shfl_xor_sync(0xFFFFFFFFu, m, o));
    float s = expf(l0 - m) + expf(l1 - m) + (has2 ? expf(l2 - m) : 0.0f);
    #pragma unroll
    for (int o = 16; o; o >>= 1) s += __shfl_xor_sync(0xFFFFFFFFu, s, o);
    m_out = m; s_out = s;
}

// ------------------- fused kernel: 80 blocks x 512 threads -------------------
__global__ void __launch_bounds__(NTHR, 1)
fused_kernel(const float* __restrict__ logits,
             const float* __restrict__ reg,
             const float* __restrict__ props,
             float* __restrict__ out) {
    extern __shared__ char sm[];
    int tid = threadIdx.x;
    int bid = blockIdx.x;
    int cls = bid + 1;

    // ---- prefetch class column (consumed after barrier; latency hidden by phase A) ----
    float pre[4];
    #pragma unroll
    for (int q = 0; q < 4; q++)
        pre[q] = logits[(tid + q * NTHR) * N_CLS + cls];   // 4*512 = 2048 exactly

    // ========== Phase A: softmax stats + proposal stats (2 rows/warp, loads batched) ====
    if (bid == 0 && tid == 0) g_cnt = 0;
    {
        int wid = tid >> 5, lane = tid & 31;
        int gwarp = bid * (NTHR / 32) + wid;       // 0..1279
        int r0 = gwarp;
        int r1 = gwarp + N_FG * (NTHR / 32);       // +1280
        bool has1 = (r1 < N_PROP);
        bool has2 = (lane + 64 < N_CLS);
        const float* lr0 = logits + r0 * N_CLS;
        const float* lr1 = logits + (has1 ? r1 : r0) * N_CLS;
        // batch all loads (MLP=6)
        float a0 = lr0[lane], a1 = lr0[lane + 32], a2 = has2 ? lr0[lane + 64] : 0.0f;
        float b0 = lr1[lane], b1 = lr1[lane + 32], b2 = has2 ? lr1[lane + 64] : 0.0f;
        float m0, s0, m1, s1;
        row_softmax(a0, a1, a2, has2, m0, s0);
        row_softmax(b0, b1, b2, has2, m1, s1);
        if (lane == 0) {
            g_rowmax[r0] = m0; g_rowsum[r0] = s0;
            const float* p = props + r0 * 4;
            float w = p[2] - p[0] + 1.0f;
            float h = p[3] - p[1] + 1.0f;
            g_prop[r0] = make_float4(w, h, p[0] + 0.5f * w, p[1] + 0.5f * h);
            if (has1) {
                g_rowmax[r1] = m1; g_rowsum[r1] = s1;
                const float* p1 = props + r1 * 4;
                float w1 = p1[2] - p1[0] + 1.0f;
                float h1 = p1[3] - p1[1] + 1.0f;
                g_prop[r1] = make_float4(w1, h1, p1[0] + 0.5f * w1, p1[1] + 0.5f * h1);
            }
        }
    }
    grid_barrier();

    // ========== Phase B: per-class threshold + rank-sort + bitmask NMS ==========
    {
        u64*    ukeys = (u64*)sm;                                   // 16KB (unsorted)
        u64*    skeys = (u64*)(sm + MAXC * 8);                      // 16KB (sorted)
        float4* sbox  = (float4*)(sm + MAXC * 16);                  // 32KB
        float*  sarea = (float*)(sm + MAXC * 32);                   // 8KB
        u64 (*mask)[NWMAX] = (u64(*)[NWMAX])(sm + MAXC * 36);       // 32KB
        u16* kept = (u16*)(sm + MAXC * 36 + BITC * NWMAX * 8);      // 1KB
        u8*  supp = (u8*)(sm + MAXC * 36 + BITC * NWMAX * 8 + BITC * 2);
        __shared__ int s_cnt, s_nk, s_base;

        if (tid == 0) s_cnt = 0;
        __syncthreads();

        #pragma unroll
        for (int q = 0; q < 4; q++) {
            int n = tid + q * NTHR;
            float p = expf(pre[q] - g_rowmax[n]) / g_rowsum[n];
            if (p > SCORE_TH) {
                int slot = atomicAdd(&s_cnt, 1);
                ukeys[slot] = ((u64)ord32(p) << 32) | (u64)(0xFFFFFFFFu - (u32)n);
            }
        }
        __syncthreads();

        int M = s_cnt;
        if (M > 0) {
            // ---- rank-sort (barrier-free O(M^2) compare, broadcast smem reads) ----
            for (int i = tid; i < M; i += NTHR) {
                u64 k = ukeys[i];
                int r = 0;
                for (int j = 0; j < M; j++) r += (ukeys[j] > k);
                skeys[r] = k;   // keys unique -> ranks distinct
            }
            __syncthreads();

            // ---- decode boxes in sorted order ----
            for (int s = tid; s < M; s += NTHR) {
                u32 n = 0xFFFFFFFFu - (u32)(skeys[s] & 0xFFFFFFFFu);
                float4 b = decode_clip(reg, (int)n, cls);
                sbox[s] = b;
                sarea[s] = (b.z - b.x + 1.0f) * (b.w - b.y + 1.0f);
            }
            __syncthreads();

            if (M <= BITC) {
                int nw = (M + 63) >> 6;
                for (int r = tid; r < M; r += NTHR) {
                    float4 bi = sbox[r];
                    float ai = sarea[r];
                    for (int q = 0; q < nw; q++) {
                        u64 wq = 0ULL;
                        int jlo = q << 6; if (jlo < r + 1) jlo = r + 1;
                        int jhi = (q << 6) + 64; if (jhi > M) jhi = M;
                        for (int j = jlo; j < jhi; j++) {
                            float4 bj = sbox[j];
                            float xx1 = fmaxf(bi.x, bj.x);
                            float yy1 = fmaxf(bi.y, bj.y);
                            float xx2 = fminf(bi.z, bj.z);
                            float yy2 = fminf(bi.w, bj.w);
                            float iw = fmaxf(xx2 - xx1 + 1.0f, 0.0f);
                            float ih = fmaxf(yy2 - yy1 + 1.0f, 0.0f);
                            float inter = iw * ih;
                            if (inter > NMS_TH * (ai + sarea[j] - inter))
                                wq |= 1ULL << (j & 63);
                        }
                        mask[r][q] = wq;
                    }
                }
                __syncthreads();

                if (M <= 64) {
                    if (tid == 0) {
                        u64 alive = (M == 64) ? ~0ULL : ((1ULL << M) - 1ULL);
                        int nk = 0;
                        while (alive) {
                            int i = __ffsll(alive) - 1;
                            kept[nk++] = (u16)i;
                            alive &= ~((1ULL << i) | mask[i][0]);
                        }
                        s_nk = nk;
                        s_base = atomicAdd(&g_cnt, nk);
                    }
                } else if (tid < 32) {
                    int lane = tid;
                    u64 rem = 0ULL;
                    int nk = 0;
                    for (int i = 0; i < M; i++) {
                        u64 rw = __shfl_sync(0xFFFFFFFFu, rem, i >> 6);
                        if (!((rw >> (i & 63)) & 1ULL)) {
                            if (lane == 0) kept[nk] = (u16)i;
                            nk++;
                            if (lane < NWMAX) rem |= mask[i][lane];
                        }
                    }
                    if (lane == 0) {
                        s_nk = nk;
                        s_base = atomicAdd(&g_cnt, nk);
                    }
                }
                __syncthreads();

                int nk = s_nk, base = s_base;
                for (int t = tid; t < nk; t += NTHR) {
                    u64 key = skeys[kept[t]];
                    u32 n = 0xFFFFFFFFu - (u32)(key & 0xFFFFFFFFu);
                    u32 flat = (u32)(cls - 1) * N_PROP + n;
                    if (base + t < CAP3)
                        g_cand[base + t] = (key & 0xFFFFFFFF00000000ULL) |
                                           (u64)(0xFFFFFFFFu - flat);
                }
            } else {
                // fallback serial greedy NMS (never triggers on this input)
                for (int i = tid; i < M; i += NTHR) supp[i] = 0;
                __syncthreads();
                for (int i = 0; i < M; i++) {
                    if (!supp[i]) {
                        float4 bi = sbox[i];
                        float ai = sarea[i];
                        if (tid == 0) {
                            u32 n = 0xFFFFFFFFu - (u32)(skeys[i] & 0xFFFFFFFFu);
                            u32 flat = (u32)(cls - 1) * N_PROP + n;
                            int pos = atomicAdd(&g_cnt, 1);
                            if (pos < CAP3)
                                g_cand[pos] = (skeys[i] & 0xFFFFFFFF00000000ULL) |
                                              (u64)(0xFFFFFFFFu - flat);
                        }
                        for (int j = i + 1 + tid; j < M; j += NTHR) {
                            if (!supp[j]) {
                                float4 bj = sbox[j];
                                float xx1 = fmaxf(bi.x, bj.x);
                                float yy1 = fmaxf(bi.y, bj.y);
                                float xx2 = fminf(bi.z, bj.z);
                                float yy2 = fminf(bi.w, bj.w);
                                float iw = fmaxf(xx2 - xx1 + 1.0f, 0.0f);
                                float ih = fmaxf(yy2 - yy1 + 1.0f, 0.0f);
                                float inter = iw * ih;
                                if (inter > NMS_TH * (ai + sarea[j] - inter)) supp[j] = 1;
                            }
                        }
                    }
                    __syncthreads();
                }
            }
        }
    }
    grid_barrier();

    // ========== Phase C: block 0 — radix select with early bucket extraction ==========
    if (bid != 0) return;
    {
        u64* keys = (u64*)sm;   // reuse: up to 128KB
        __shared__ u32 hist[256];
        __shared__ u64 ext[EXTC];
        __shared__ u64 s_prefix, s_T;
        __shared__ int s_r, s_cnt, s_K, s_selcnt, s_ecnt;
        __shared__ u64 sel[DETS];

        int K = g_cnt;
        if (K > CAP3) K = CAP3;
        for (int i = tid; i < K; i += NTHR) keys[i] = g_cand[i];
        if (tid == 0) { s_prefix = 0ULL; s_r = DETS; s_selcnt = 0; s_K = K; s_cnt = 0; }
        __syncthreads();

        // fallback fill (reference's -1-masked top_k): only when fewer than 100 kept
        if (tid == 0 && K < DETS) {
            int kk = K, f = 0;
            while (kk < DETS && f < FLAT_TOT) {
                bool found = false;
                for (int q = 0; q < K; q++) {
                    u32 fl = 0xFFFFFFFFu - (u32)(keys[q] & 0xFFFFFFFFu);
                    if ((int)fl == f) { found = true; break; }
                }
                if (!found)
                    keys[kk++] = ((u64)ord32(-1.0f) << 32) | (u64)(0xFFFFFFFFu - (u32)f);
                f++;
            }
            s_K = kk;
        }
        __syncthreads();
        K = s_K;

        // MSB-first 8-bit radix; exit as soon as target bucket has <= EXTC keys
        bool done = false;
        for (int shift = 56; shift >= 0 && !done; shift -= 8) {
            if (tid < 256) hist[tid] = 0;
            __syncthreads();
            u64 hm  = (shift == 56) ? 0ULL : (~0ULL) << (shift + 8);
            u64 pfx = s_prefix;
            for (int base = 0; base < K; base += NTHR) {
                int i = base + tid;
                bool v = (i < K);
                u64 k = v ? keys[i] : 0ULL;
                bool mt = v && ((k & hm) == pfx);
                u32 b = mt ? (u32)((k >> shift) & 255u) : 0xFFFFFFFFu;
                u32 grp = __match_any_sync(0xFFFFFFFFu, b);
                if (mt && ((__ffs(grp) - 1) == (tid & 31)))
                    atomicAdd(&hist[b], __popc(grp));
            }
            __syncthreads();
            if (tid < 32) {
                int r0 = s_r;
                __syncwarp();
                u32 h[8]; u32 cs = 0;
                #pragma unroll
                for (int q = 0; q < 8; q++) { h[q] = hist[tid * 8 + q]; cs += h[q]; }
                u32 p = cs;
                #pragma unroll
                for (int o = 1; o < 32; o <<= 1) {
                    u32 vv = __shfl_up_sync(0xFFFFFFFFu, p, o);
                    if (tid >= o) p += vv;
                }
                u32 total = __shfl_sync(0xFFFFFFFFu, p, 31);
                u32 run = total - p;
                int chosen = -1; u32 newr = 0, cinb = 0;
                #pragma unroll
                for (int q = 7; q >= 0; q--) {
                    if (chosen < 0 && run < (u32)r0 && (u32)r0 <= run + h[q]) {
                        chosen = tid * 8 + q; newr = (u32)r0 - run; cinb = h[q];
                    }
                    run += h[q];
                }
                if (chosen >= 0) {
                    s_prefix = pfx | ((u64)(u32)chosen << shift);
                    s_r = (int)newr;
                    s_cnt = (int)cinb;
                }
            }
            __syncthreads();
            if (s_cnt <= EXTC) {
                // extract bucket, rank-compare for the exact 100th key
                if (tid == 0) s_ecnt = 0;
                __syncthreads();
                u64 hm2 = (shift == 0) ? ~0ULL : (~0ULL) << shift;
                u64 pfx2 = s_prefix;
                for (int i = tid; i < K; i += NTHR) {
                    u64 k = keys[i];
                    if ((k & hm2) == pfx2) {
                        int e = atomicAdd(&s_ecnt, 1);
                        if (e < EXTC) ext[e] = k;
                    }
                }
                __syncthreads();
                int B = s_ecnt; if (B > EXTC) B = EXTC;
                int r = s_r;
                if (tid < B) {
                    u64 mk = ext[tid];
                    int rk = 0;
                    for (int q = 0; q < B; q++) rk += (ext[q] > mk);
                    if (rk == r - 1) s_T = mk;
                }
                done = true;
            }
            __syncthreads();
        }
        u64 T = s_T;

        // exactly 100 keys >= T (keys unique)
        for (int i = tid; i < K; i += NTHR) {
            u64 k = keys[i];
            if (k >= T) {
                int s = atomicAdd(&s_selcnt, 1);
                if (s < DETS) sel[s] = k;
            }
        }
        __syncthreads();

        if (tid < DETS) {
            u64 my = sel[tid];
            int rank = 0;
            for (int q = 0; q < DETS; q++) rank += (sel[q] > my);
            u32 flat = 0xFFFFFFFFu - (u32)(my & 0xFFFFFFFFu);
            float score = unord32((u32)(my >> 32));
            int c = (int)(flat >> 11);
            int n = (int)(flat & (N_PROP - 1));
            float4 b = decode_clip(reg, n, c + 1);
            out[rank * 4 + 0] = b.x;
            out[rank * 4 + 1] = b.y;
            out[rank * 4 + 2] = b.z;
            out[rank * 4 + 3] = b.w;
            out[DETS * 4 + rank] = score;
            out[DETS * 5 + rank] = (float)(c + 1);
        }
    }
}

// ------------------- launch -------------------
extern "C" void kernel_launch(void* const* d_in, const int* in_sizes, int n_in,
                              void* d_out, int out_size) {
    const float* logits = (const float*)d_in[0];
    const float* reg    = (const float*)d_in[1];
    const float* props  = (const float*)d_in[2];
    float* out = (float*)d_out;

    size_t smem = (size_t)CAP3 * sizeof(u64);  // 128KB
    cudaFuncSetAttribute(fused_kernel, cudaFuncAttributeMaxDynamicSharedMemorySize, (int)smem);
    fused_kernel<<<N_FG, NTHR, smem>>>(logits, reg, props, out);
}